// round 2
// baseline (speedup 1.0000x reference)
#include <cuda_runtime.h>
#include <cstdint>
#include <math_constants.h>

// Problem constants
#define BB 4
#define SS 2048
#define EE 1024
#define HH 16
#define DD 64
// rows of the flattened token matrix
#define MROWS (BB * SS)      // 8192
#define QKVN  (3 * HH * DD)  // 3072

// Scratch (allocation-free rule: __device__ globals)
__device__ float g_qkv[(size_t)MROWS * QKVN]; // 96 MB
__device__ float g_z[(size_t)MROWS * EE];     // 32 MB  (scrambled-layout z)

// ---------------------------------------------------------------------------
// SGEMM: C[M,N] = A[M,K] @ B[K,N], row-major, all dims multiples of tile.
// BM=BN=128, BK=16, 256 threads, 8x8 register tile per thread.
// ---------------------------------------------------------------------------
__global__ __launch_bounds__(256) void sgemm_kernel(
    const float* __restrict__ A, const float* __restrict__ Bm,
    float* __restrict__ C, int M, int N, int K)
{
    __shared__ float As[16][132];
    __shared__ float Bs[16][132];

    const int tid = threadIdx.x;
    const int tx = tid & 15;
    const int ty = tid >> 4;
    const int m0 = blockIdx.y * 128;
    const int n0 = blockIdx.x * 128;

    float acc[8][8];
#pragma unroll
    for (int i = 0; i < 8; i++)
#pragma unroll
        for (int j = 0; j < 8; j++) acc[i][j] = 0.f;

    for (int k0 = 0; k0 < K; k0 += 16) {
        // Load A tile (128x16) transposed into As[k][m]
#pragma unroll
        for (int i = 0; i < 2; i++) {
            int f = i * 256 + tid;          // 0..511 float4s
            int m = f >> 2;                 // 0..127
            int kq = (f & 3) * 4;           // 0,4,8,12
            float4 v = *(const float4*)(A + (size_t)(m0 + m) * K + k0 + kq);
            As[kq + 0][m] = v.x;
            As[kq + 1][m] = v.y;
            As[kq + 2][m] = v.z;
            As[kq + 3][m] = v.w;
        }
        // Load B tile (16x128) into Bs[k][n]
#pragma unroll
        for (int i = 0; i < 2; i++) {
            int f = i * 256 + tid;          // 0..511 float4s
            int kk = f >> 5;                // 0..15
            int nq = (f & 31) * 4;          // 0..124
            *(float4*)(&Bs[kk][nq]) =
                *(const float4*)(Bm + (size_t)(k0 + kk) * N + n0 + nq);
        }
        __syncthreads();

#pragma unroll
        for (int kk = 0; kk < 16; kk++) {
            float ra[8], rb[8];
            *(float4*)(ra)     = *(const float4*)(&As[kk][ty * 8]);
            *(float4*)(ra + 4) = *(const float4*)(&As[kk][ty * 8 + 4]);
            *(float4*)(rb)     = *(const float4*)(&Bs[kk][tx * 8]);
            *(float4*)(rb + 4) = *(const float4*)(&Bs[kk][tx * 8 + 4]);
#pragma unroll
            for (int i = 0; i < 8; i++)
#pragma unroll
                for (int j = 0; j < 8; j++)
                    acc[i][j] += ra[i] * rb[j];
        }
        __syncthreads();
    }

#pragma unroll
    for (int i = 0; i < 8; i++) {
        float* cp = C + (size_t)(m0 + ty * 8 + i) * N + n0 + tx * 8;
        float4 v0, v1;
        v0.x = acc[i][0]; v0.y = acc[i][1]; v0.z = acc[i][2]; v0.w = acc[i][3];
        v1.x = acc[i][4]; v1.y = acc[i][5]; v1.z = acc[i][6]; v1.w = acc[i][7];
        *(float4*)(cp)     = v0;
        *(float4*)(cp + 4) = v1;
    }
}

// ---------------------------------------------------------------------------
// Flash attention over qkv scratch.
// grid = (B*H, S/64), block = 256.
// Each block: 64 query rows, loops over 32-key tiles, online softmax.
// Writes z in the reference's faithful "bug" layout:
//   z[b, h*128 + s/16, (s%16)*64 + d]
// ---------------------------------------------------------------------------
__global__ __launch_bounds__(256) void attn_kernel(
    const float* __restrict__ qkv, float* __restrict__ z)
{
    __shared__ float Qs[64][68];
    __shared__ float Ks[32][68];
    __shared__ float Vs[32][68];
    __shared__ float Ps[64][33];

    const int bh = blockIdx.x;
    const int b = bh >> 4;       // / HH
    const int h = bh & 15;       // % HH
    const int s0 = blockIdx.y * 64;
    const int tid = threadIdx.x;
    const int r = tid >> 2;      // query row 0..63
    const int quad = tid & 3;    // 4 lanes per row
    const int cb = quad * 8;     // score cols handled by this lane
    const int db = quad * 16;    // output dims handled by this lane

    const float* base = qkv + (size_t)b * SS * QKVN + h * DD;

    // Load Q tile [64 x 64]
#pragma unroll
    for (int i = 0; i < 4; i++) {
        int f = i * 256 + tid;          // 0..1023 float4s
        int rr = f >> 4;
        int c4 = (f & 15) << 2;
        *(float4*)(&Qs[rr][c4]) =
            *(const float4*)(base + (size_t)(s0 + rr) * QKVN + c4);
    }

    float m = -CUDART_INF_F;
    float l = 0.f;
    float o[16];
#pragma unroll
    for (int j = 0; j < 16; j++) o[j] = 0.f;

    for (int kt = 0; kt < SS; kt += 32) {
        __syncthreads();  // protect Ks/Vs (and first-iter Q) reuse
        // Load K,V tiles [32 x 64] each
#pragma unroll
        for (int i = 0; i < 2; i++) {
            int f = i * 256 + tid;      // 0..511 float4s
            int t = f >> 4;
            int c4 = (f & 15) << 2;
            const float* row = base + (size_t)(kt + t) * QKVN + c4;
            *(float4*)(&Ks[t][c4]) = *(const float4*)(row + 1024);
            *(float4*)(&Vs[t][c4]) = *(const float4*)(row + 2048);
        }
        __syncthreads();

        // scores s[r][cb..cb+7]
        float sc[8];
#pragma unroll
        for (int c = 0; c < 8; c++) sc[c] = 0.f;
#pragma unroll
        for (int d4 = 0; d4 < 16; d4++) {
            float4 qv = *(const float4*)(&Qs[r][d4 * 4]);
#pragma unroll
            for (int c = 0; c < 8; c++) {
                float4 kv = *(const float4*)(&Ks[cb + c][d4 * 4]);
                sc[c] += qv.x * kv.x + qv.y * kv.y + qv.z * kv.z + qv.w * kv.w;
            }
        }
        float mt = -CUDART_INF_F;
#pragma unroll
        for (int c = 0; c < 8; c++) {
            sc[c] *= 0.125f;            // HEAD_DIM^-0.5
            mt = fmaxf(mt, sc[c]);
        }
        mt = fmaxf(mt, __shfl_xor_sync(0xffffffffu, mt, 1));
        mt = fmaxf(mt, __shfl_xor_sync(0xffffffffu, mt, 2));
        float mnew = fmaxf(m, mt);
        float corr = __expf(m - mnew);
        float ls = 0.f;
#pragma unroll
        for (int c = 0; c < 8; c++) {
            float p = __expf(sc[c] - mnew);
            Ps[r][cb + c] = p;
            ls += p;
        }
        ls += __shfl_xor_sync(0xffffffffu, ls, 1);
        ls += __shfl_xor_sync(0xffffffffu, ls, 2);
        l = l * corr + ls;
        m = mnew;
#pragma unroll
        for (int j = 0; j < 16; j++) o[j] *= corr;

        __syncwarp();  // Ps row written by this row's 4 lanes (same warp)

        // O[r][db..db+15] += P[r][t] * V[t][db..db+15]
#pragma unroll
        for (int t = 0; t < 32; t++) {
            float p = Ps[r][t];
#pragma unroll
            for (int j4 = 0; j4 < 4; j4++) {
                float4 v = *(const float4*)(&Vs[t][db + j4 * 4]);
                o[j4 * 4 + 0] += p * v.x;
                o[j4 * 4 + 1] += p * v.y;
                o[j4 * 4 + 2] += p * v.z;
                o[j4 * 4 + 3] += p * v.w;
            }
        }
    }

    // Normalize and store in the scrambled reference layout
    float inv = 1.f / l;
    int sg = s0 + r;
    int zrow = h * 128 + (sg >> 4);
    int col = (sg & 15) * 64 + db;
    float* dst = z + ((size_t)b * SS + zrow) * EE + col;
#pragma unroll
    for (int j4 = 0; j4 < 4; j4++) {
        float4 v;
        v.x = o[j4 * 4 + 0] * inv;
        v.y = o[j4 * 4 + 1] * inv;
        v.z = o[j4 * 4 + 2] * inv;
        v.w = o[j4 * 4 + 3] * inv;
        *(float4*)(dst + j4 * 4) = v;
    }
}

// ---------------------------------------------------------------------------
extern "C" void kernel_launch(void* const* d_in, const int* in_sizes, int n_in,
                              void* d_out, int out_size)
{
    (void)in_sizes; (void)n_in; (void)out_size;
    const float* x    = (const float*)d_in[0];  // [B,S,E] fp32
    const float* Wqkv = (const float*)d_in[1];  // [E, 3*H*D]
    const float* Wout = (const float*)d_in[2];  // [H*D, E]
    float* out = (float*)d_out;                 // [B,S,E] fp32

    void* p_qkv = nullptr;
    void* p_z   = nullptr;
    cudaGetSymbolAddress(&p_qkv, g_qkv);
    cudaGetSymbolAddress(&p_z, g_z);
    float* qkv = (float*)p_qkv;
    float* zb  = (float*)p_z;

    dim3 blk(256);
    // 1) QKV projection: [8192,1024] @ [1024,3072]
    sgemm_kernel<<<dim3(QKVN / 128, MROWS / 128), blk>>>(x, Wqkv, qkv,
                                                         MROWS, QKVN, EE);
    // 2) Attention (writes scrambled z)
    attn_kernel<<<dim3(BB * HH, SS / 64), blk>>>(qkv, zb);
    // 3) Output projection: [8192,1024] @ [1024,1024]
    sgemm_kernel<<<dim3(EE / 128, MROWS / 128), blk>>>(zb, Wout, out,
                                                       MROWS, EE, EE);
}

// round 3
// speedup vs baseline: 11.2345x; 11.2345x over previous
#include <cuda_runtime.h>
#include <cstdint>
#include <math_constants.h>

// Problem constants
#define BB 4
#define SS 2048
#define EE 1024
#define HH 16
#define DD 64
#define MROWS (BB * SS)      // 8192
#define QKVN  (3 * HH * DD)  // 3072

// Scratch (allocation-free rule: __device__ globals)
__device__ float g_qkv[(size_t)MROWS * QKVN]; // 96 MB
__device__ float g_z[(size_t)MROWS * EE];     // 32 MB (scrambled-layout z)

__device__ __forceinline__ uint32_t f2tf32(float x) {
    uint32_t r;
    asm("cvt.rna.tf32.f32 %0, %1;" : "=r"(r) : "f"(x));
    return r;
}

__device__ __forceinline__ void mma_tf32(float d[4], const uint32_t a[4],
                                         const uint32_t b[2]) {
    asm volatile(
        "mma.sync.aligned.m16n8k8.row.col.f32.tf32.tf32.f32 "
        "{%0,%1,%2,%3}, {%4,%5,%6,%7}, {%8,%9}, {%0,%1,%2,%3};\n"
        : "+f"(d[0]), "+f"(d[1]), "+f"(d[2]), "+f"(d[3])
        : "r"(a[0]), "r"(a[1]), "r"(a[2]), "r"(a[3]), "r"(b[0]), "r"(b[1]));
}

// ---------------------------------------------------------------------------
// tf32 tensor-core GEMM: C[M,N] = A[M,K] @ B[K,N], row-major.
// BM=128, BN=128, BK=32, 256 threads (8 warps, 4x2), warp tile 32x64.
// ---------------------------------------------------------------------------
__global__ __launch_bounds__(256, 2) void tgemm_kernel(
    const float* __restrict__ A, const float* __restrict__ Bm,
    float* __restrict__ C, int M, int N, int K)
{
    __shared__ uint32_t As[128][36];  // [m][k], pad 36 -> conflict-free frags
    __shared__ uint32_t Bs[32][136];  // [k][n], pad 136 -> conflict-free frags

    const int tid = threadIdx.x;
    const int lane = tid & 31;
    const int wid = tid >> 5;
    const int wm = wid & 3;   // warp row (4)
    const int wn = wid >> 2;  // warp col (2)
    const int r = lane >> 2;
    const int cq = lane & 3;
    const int m0 = blockIdx.y * 128;
    const int n0 = blockIdx.x * 128;

    float acc[2][8][4];
#pragma unroll
    for (int i = 0; i < 2; i++)
#pragma unroll
        for (int j = 0; j < 8; j++)
#pragma unroll
            for (int q = 0; q < 4; q++) acc[i][j][q] = 0.f;

    for (int k0 = 0; k0 < K; k0 += 32) {
        // A tile 128x32 -> As[m][k]
#pragma unroll
        for (int i = 0; i < 4; i++) {
            int f = i * 256 + tid;
            int m = f >> 3;
            int kq = (f & 7) * 4;
            float4 v = *(const float4*)(A + (size_t)(m0 + m) * K + k0 + kq);
            uint4 u;
            u.x = f2tf32(v.x); u.y = f2tf32(v.y);
            u.z = f2tf32(v.z); u.w = f2tf32(v.w);
            *(uint4*)(&As[m][kq]) = u;
        }
        // B tile 32x128 -> Bs[k][n]
#pragma unroll
        for (int i = 0; i < 4; i++) {
            int f = i * 256 + tid;
            int kk = f >> 5;
            int nq = (f & 31) * 4;
            float4 v = *(const float4*)(Bm + (size_t)(k0 + kk) * N + n0 + nq);
            uint4 u;
            u.x = f2tf32(v.x); u.y = f2tf32(v.y);
            u.z = f2tf32(v.z); u.w = f2tf32(v.w);
            *(uint4*)(&Bs[kk][nq]) = u;
        }
        __syncthreads();

#pragma unroll
        for (int ks = 0; ks < 4; ks++) {
            uint32_t af[2][4];
#pragma unroll
            for (int im = 0; im < 2; im++) {
                int mr = wm * 32 + im * 16 + r;
                af[im][0] = As[mr][ks * 8 + cq];
                af[im][1] = As[mr + 8][ks * 8 + cq];
                af[im][2] = As[mr][ks * 8 + cq + 4];
                af[im][3] = As[mr + 8][ks * 8 + cq + 4];
            }
            uint32_t bf[8][2];
#pragma unroll
            for (int in_ = 0; in_ < 8; in_++) {
                int nc = wn * 64 + in_ * 8 + r;
                bf[in_][0] = Bs[ks * 8 + cq][nc];
                bf[in_][1] = Bs[ks * 8 + cq + 4][nc];
            }
#pragma unroll
            for (int im = 0; im < 2; im++)
#pragma unroll
                for (int in_ = 0; in_ < 8; in_++)
                    mma_tf32(acc[im][in_], af[im], bf[in_]);
        }
        __syncthreads();
    }

    // Epilogue
#pragma unroll
    for (int im = 0; im < 2; im++) {
#pragma unroll
        for (int in_ = 0; in_ < 8; in_++) {
            int row = m0 + wm * 32 + im * 16 + r;
            int col = n0 + wn * 64 + in_ * 8 + 2 * cq;
            *(float2*)(C + (size_t)row * N + col) =
                make_float2(acc[im][in_][0], acc[im][in_][1]);
            *(float2*)(C + (size_t)(row + 8) * N + col) =
                make_float2(acc[im][in_][2], acc[im][in_][3]);
        }
    }
}

// ---------------------------------------------------------------------------
// Flash attention, tf32 tensor cores.
// grid = (B*H, S/128), block = 256 (8 warps). Warp owns 16 query rows.
// KV tile = 64. Online softmax. P relayout C-frag -> A-frag via shuffles.
// Writes z in scrambled reference layout: z[b, h*128+s/16, (s%16)*64+d]
// ---------------------------------------------------------------------------
__global__ __launch_bounds__(256) void attn_kernel(
    const float* __restrict__ qkv, float* __restrict__ z)
{
    __shared__ uint32_t Ks[64][68];  // [t][d], pad 68
    __shared__ uint32_t Vs[64][72];  // [t][d], pad 72

    const int bh = blockIdx.x;
    const int b = bh >> 4;
    const int h = bh & 15;
    const int s0 = blockIdx.y * 128;
    const int tid = threadIdx.x;
    const int lane = tid & 31;
    const int warp = tid >> 5;
    const int r = lane >> 2;
    const int cq = lane & 3;

    const float* base = qkv + (size_t)b * SS * QKVN + h * DD;

    // Q fragments (scaled by 1/8, tf32-rounded), kept in registers
    uint32_t qa[8][4];
    {
        const int row0 = s0 + warp * 16 + r;
        const float* q0 = base + (size_t)row0 * QKVN;
        const float* q1 = base + (size_t)(row0 + 8) * QKVN;
#pragma unroll
        for (int kf = 0; kf < 8; kf++) {
            qa[kf][0] = f2tf32(0.125f * q0[kf * 8 + cq]);
            qa[kf][1] = f2tf32(0.125f * q1[kf * 8 + cq]);
            qa[kf][2] = f2tf32(0.125f * q0[kf * 8 + cq + 4]);
            qa[kf][3] = f2tf32(0.125f * q1[kf * 8 + cq + 4]);
        }
    }

    float o[8][4];
#pragma unroll
    for (int nt = 0; nt < 8; nt++)
#pragma unroll
        for (int q = 0; q < 4; q++) o[nt][q] = 0.f;
    float mrow0 = -1e30f, mrow1 = -1e30f;
    float lrow0 = 0.f, lrow1 = 0.f;

    for (int kt = 0; kt < SS; kt += 64) {
        __syncthreads();
        // Load K,V tiles [64 x 64] (tf32-rounded)
#pragma unroll
        for (int i = 0; i < 4; i++) {
            int f = i * 256 + tid;
            int t = f >> 4;
            int c4 = (f & 15) * 4;
            const float* row = base + (size_t)(kt + t) * QKVN + c4;
            float4 kv = *(const float4*)(row + 1024);
            float4 vv = *(const float4*)(row + 2048);
            uint4 uk, uv;
            uk.x = f2tf32(kv.x); uk.y = f2tf32(kv.y);
            uk.z = f2tf32(kv.z); uk.w = f2tf32(kv.w);
            uv.x = f2tf32(vv.x); uv.y = f2tf32(vv.y);
            uv.z = f2tf32(vv.z); uv.w = f2tf32(vv.w);
            *(uint4*)(&Ks[t][c4]) = uk;
            *(uint4*)(&Vs[t][c4]) = uv;
        }
        __syncthreads();

        // S = Q @ K^T   (warp: 16 x 64)
        float s[8][4];
#pragma unroll
        for (int nt = 0; nt < 8; nt++)
#pragma unroll
            for (int q = 0; q < 4; q++) s[nt][q] = 0.f;
#pragma unroll
        for (int kf = 0; kf < 8; kf++) {
#pragma unroll
            for (int nt = 0; nt < 8; nt++) {
                uint32_t bf[2];
                bf[0] = Ks[nt * 8 + r][kf * 8 + cq];
                bf[1] = Ks[nt * 8 + r][kf * 8 + cq + 4];
                mma_tf32(s[nt], qa[kf], bf);
            }
        }

        // Online softmax (rows r and r+8 of this warp's 16-row block)
        float mt0 = -1e30f, mt1 = -1e30f;
#pragma unroll
        for (int nt = 0; nt < 8; nt++) {
            mt0 = fmaxf(mt0, fmaxf(s[nt][0], s[nt][1]));
            mt1 = fmaxf(mt1, fmaxf(s[nt][2], s[nt][3]));
        }
        mt0 = fmaxf(mt0, __shfl_xor_sync(0xffffffffu, mt0, 1));
        mt0 = fmaxf(mt0, __shfl_xor_sync(0xffffffffu, mt0, 2));
        mt1 = fmaxf(mt1, __shfl_xor_sync(0xffffffffu, mt1, 1));
        mt1 = fmaxf(mt1, __shfl_xor_sync(0xffffffffu, mt1, 2));
        float mn0 = fmaxf(mrow0, mt0);
        float mn1 = fmaxf(mrow1, mt1);
        float corr0 = __expf(mrow0 - mn0);
        float corr1 = __expf(mrow1 - mn1);
        float ls0 = 0.f, ls1 = 0.f;
        uint32_t up[8][4];
#pragma unroll
        for (int nt = 0; nt < 8; nt++) {
            float p0 = __expf(s[nt][0] - mn0);
            float p1 = __expf(s[nt][1] - mn0);
            float p2 = __expf(s[nt][2] - mn1);
            float p3 = __expf(s[nt][3] - mn1);
            ls0 += p0 + p1;
            ls1 += p2 + p3;
            up[nt][0] = f2tf32(p0);
            up[nt][1] = f2tf32(p1);
            up[nt][2] = f2tf32(p2);
            up[nt][3] = f2tf32(p3);
        }
        ls0 += __shfl_xor_sync(0xffffffffu, ls0, 1);
        ls0 += __shfl_xor_sync(0xffffffffu, ls0, 2);
        ls1 += __shfl_xor_sync(0xffffffffu, ls1, 1);
        ls1 += __shfl_xor_sync(0xffffffffu, ls1, 2);
        lrow0 = lrow0 * corr0 + ls0;
        lrow1 = lrow1 * corr1 + ls1;
        mrow0 = mn0;
        mrow1 = mn1;
#pragma unroll
        for (int nt = 0; nt < 8; nt++) {
            o[nt][0] *= corr0;
            o[nt][1] *= corr0;
            o[nt][2] *= corr1;
            o[nt][3] *= corr1;
        }

        // O += P @ V. Relayout P (C-frag) -> A-frag via intra-quad shuffles.
        const int src1 = (lane & ~3) | (cq >> 1);
        const int src2 = src1 + 2;
        const bool oddc = (cq & 1);
#pragma unroll
        for (int ks = 0; ks < 8; ks++) {
            uint32_t pa[4];
            {
                uint32_t v0 = __shfl_sync(0xffffffffu, up[ks][0], src1);
                uint32_t v1 = __shfl_sync(0xffffffffu, up[ks][1], src1);
                pa[0] = oddc ? v1 : v0;
                uint32_t w0 = __shfl_sync(0xffffffffu, up[ks][0], src2);
                uint32_t w1 = __shfl_sync(0xffffffffu, up[ks][1], src2);
                pa[2] = oddc ? w1 : w0;
                uint32_t x0 = __shfl_sync(0xffffffffu, up[ks][2], src1);
                uint32_t x1 = __shfl_sync(0xffffffffu, up[ks][3], src1);
                pa[1] = oddc ? x1 : x0;
                uint32_t y0 = __shfl_sync(0xffffffffu, up[ks][2], src2);
                uint32_t y1 = __shfl_sync(0xffffffffu, up[ks][3], src2);
                pa[3] = oddc ? y1 : y0;
            }
#pragma unroll
            for (int nt = 0; nt < 8; nt++) {
                uint32_t bf[2];
                bf[0] = Vs[ks * 8 + cq][nt * 8 + r];
                bf[1] = Vs[ks * 8 + cq + 4][nt * 8 + r];
                mma_tf32(o[nt], pa, bf);
            }
        }
    }

    // Epilogue: normalize and write scrambled layout
    float inv0 = 1.f / lrow0;
    float inv1 = 1.f / lrow1;
    int sg0 = s0 + warp * 16 + r;
    int sg1 = sg0 + 8;
    int zr0 = h * 128 + (sg0 >> 4);
    int zr1 = h * 128 + (sg1 >> 4);
    float* d0 = z + ((size_t)b * SS + zr0) * EE + (sg0 & 15) * 64;
    float* d1 = z + ((size_t)b * SS + zr1) * EE + (sg1 & 15) * 64;
#pragma unroll
    for (int nt = 0; nt < 8; nt++) {
        int col = nt * 8 + 2 * cq;
        *(float2*)(d0 + col) = make_float2(o[nt][0] * inv0, o[nt][1] * inv0);
        *(float2*)(d1 + col) = make_float2(o[nt][2] * inv1, o[nt][3] * inv1);
    }
}

// ---------------------------------------------------------------------------
extern "C" void kernel_launch(void* const* d_in, const int* in_sizes, int n_in,
                              void* d_out, int out_size)
{
    (void)in_sizes; (void)n_in; (void)out_size;
    const float* x    = (const float*)d_in[0];  // [B,S,E] fp32
    const float* Wqkv = (const float*)d_in[1];  // [E, 3*H*D]
    const float* Wout = (const float*)d_in[2];  // [H*D, E]
    float* out = (float*)d_out;                 // [B,S,E] fp32

    void* p_qkv = nullptr;
    void* p_z   = nullptr;
    cudaGetSymbolAddress(&p_qkv, g_qkv);
    cudaGetSymbolAddress(&p_z, g_z);
    float* qkv = (float*)p_qkv;
    float* zb  = (float*)p_z;

    dim3 blk(256);
    // 1) QKV projection: [8192,1024] @ [1024,3072]
    tgemm_kernel<<<dim3(QKVN / 128, MROWS / 128), blk>>>(x, Wqkv, qkv,
                                                         MROWS, QKVN, EE);
    // 2) Attention (writes scrambled z)
    attn_kernel<<<dim3(BB * HH, SS / 128), blk>>>(qkv, zb);
    // 3) Output projection: [8192,1024] @ [1024,1024]
    tgemm_kernel<<<dim3(EE / 128, MROWS / 128), blk>>>(zb, Wout, out,
                                                       MROWS, EE, EE);
}

// round 4
// speedup vs baseline: 13.2119x; 1.1760x over previous
#include <cuda_runtime.h>
#include <cstdint>
#include <math_constants.h>

// Problem constants
#define BB 4
#define SS 2048
#define EE 1024
#define HH 16
#define DD 64
#define MROWS (BB * SS)      // 8192
#define QKVN  (3 * HH * DD)  // 3072

// Scratch (allocation-free rule: __device__ globals)
__device__ float g_qkv[(size_t)MROWS * QKVN]; // 96 MB (tf32-rounded values)
__device__ float g_z[(size_t)MROWS * EE];     // 32 MB (scrambled z, tf32-rounded)
__device__ float g_xr[(size_t)MROWS * EE];    // 32 MB (tf32-rounded x)
__device__ float g_wqkv[(size_t)EE * QKVN];   // 12 MB (tf32-rounded W_qkv)
__device__ float g_wout[(size_t)EE * EE];     //  4 MB (tf32-rounded W_out)

__device__ __forceinline__ uint32_t f2tf32(float x) {
    uint32_t r;
    asm("cvt.rna.tf32.f32 %0, %1;" : "=r"(r) : "f"(x));
    return r;
}
__device__ __forceinline__ float ex2(float x) {
    float y;
    asm("ex2.approx.f32 %0, %1;" : "=f"(y) : "f"(x));
    return y;
}
__device__ __forceinline__ void cp16(void* dst, const void* src) {
    uint32_t d = (uint32_t)__cvta_generic_to_shared(dst);
    asm volatile("cp.async.cg.shared.global [%0], [%1], 16;" :: "r"(d), "l"(src));
}
#define CP_COMMIT() asm volatile("cp.async.commit_group;")
#define CP_WAIT0()  asm volatile("cp.async.wait_group 0;")

__device__ __forceinline__ void mma_tf32(float d[4], const uint32_t a[4],
                                         const uint32_t b[2]) {
    asm volatile(
        "mma.sync.aligned.m16n8k8.row.col.f32.tf32.tf32.f32 "
        "{%0,%1,%2,%3}, {%4,%5,%6,%7}, {%8,%9}, {%0,%1,%2,%3};\n"
        : "+f"(d[0]), "+f"(d[1]), "+f"(d[2]), "+f"(d[3])
        : "r"(a[0]), "r"(a[1]), "r"(a[2]), "r"(a[3]), "r"(b[0]), "r"(b[1]));
}
#define F2U __float_as_uint

// ---------------------------------------------------------------------------
// Pre-round fp32 -> tf32-valued fp32
// ---------------------------------------------------------------------------
__global__ void round_tf32_kernel(const float4* __restrict__ src,
                                  float4* __restrict__ dst, int n4) {
    int i = blockIdx.x * blockDim.x + threadIdx.x;
    if (i < n4) {
        float4 v = src[i];
        float4 o;
        o.x = __uint_as_float(f2tf32(v.x));
        o.y = __uint_as_float(f2tf32(v.y));
        o.z = __uint_as_float(f2tf32(v.z));
        o.w = __uint_as_float(f2tf32(v.w));
        dst[i] = o;
    }
}

// ---------------------------------------------------------------------------
// tf32 tensor-core GEMM, inputs pre-rounded. cp.async double-buffered.
// BM=128, BN=128, BK=32, 256 threads (8 warps 4x2), warp tile 32x64.
// Dynamic SMEM: As[2][128][36] + Bs[2][32][136] = 71680 B.
// ---------------------------------------------------------------------------
__global__ __launch_bounds__(256, 2) void tgemm_kernel(
    const float* __restrict__ A, const float* __restrict__ Bm,
    float* __restrict__ C, int M, int N, int K, int round_out)
{
    extern __shared__ float sm_g[];
    typedef float AsT[128][36];
    typedef float BsT[32][136];
    AsT* As = (AsT*)sm_g;                       // 2 stages
    BsT* Bs = (BsT*)(sm_g + 2 * 128 * 36);

    const int tid = threadIdx.x;
    const int lane = tid & 31;
    const int wid = tid >> 5;
    const int wm = wid & 3;
    const int wn = wid >> 2;
    const int r = lane >> 2;
    const int cq = lane & 3;
    const int m0 = blockIdx.y * 128;
    const int n0 = blockIdx.x * 128;

    float acc[2][8][4];
#pragma unroll
    for (int i = 0; i < 2; i++)
#pragma unroll
        for (int j = 0; j < 8; j++)
#pragma unroll
            for (int q = 0; q < 4; q++) acc[i][j][q] = 0.f;

    auto load_tile = [&](int buf, int k0) {
#pragma unroll
        for (int i = 0; i < 4; i++) {           // A: 128x32 = 1024 chunks
            int f = i * 256 + tid;
            int m = f >> 3;
            int kq = (f & 7) * 4;
            cp16(&As[buf][m][kq], A + (size_t)(m0 + m) * K + k0 + kq);
        }
#pragma unroll
        for (int i = 0; i < 4; i++) {           // B: 32x128 = 1024 chunks
            int f = i * 256 + tid;
            int kk = f >> 5;
            int nq = (f & 31) * 4;
            cp16(&Bs[buf][kk][nq], Bm + (size_t)(k0 + kk) * N + n0 + nq);
        }
        CP_COMMIT();
    };

    const int ntiles = K / 32;
    load_tile(0, 0);

    for (int it = 0; it < ntiles; it++) {
        const int cur = it & 1;
        CP_WAIT0();
        __syncthreads();
        if (it + 1 < ntiles) load_tile(cur ^ 1, (it + 1) * 32);

#pragma unroll
        for (int ks = 0; ks < 4; ks++) {
            uint32_t af[2][4];
#pragma unroll
            for (int im = 0; im < 2; im++) {
                int mr = wm * 32 + im * 16 + r;
                af[im][0] = F2U(As[cur][mr][ks * 8 + cq]);
                af[im][1] = F2U(As[cur][mr + 8][ks * 8 + cq]);
                af[im][2] = F2U(As[cur][mr][ks * 8 + cq + 4]);
                af[im][3] = F2U(As[cur][mr + 8][ks * 8 + cq + 4]);
            }
            uint32_t bf[8][2];
#pragma unroll
            for (int in_ = 0; in_ < 8; in_++) {
                int nc = wn * 64 + in_ * 8 + r;
                bf[in_][0] = F2U(Bs[cur][ks * 8 + cq][nc]);
                bf[in_][1] = F2U(Bs[cur][ks * 8 + cq + 4][nc]);
            }
#pragma unroll
            for (int im = 0; im < 2; im++)
#pragma unroll
                for (int in_ = 0; in_ < 8; in_++)
                    mma_tf32(acc[im][in_], af[im], bf[in_]);
        }
    }

    // Epilogue (optionally tf32-round outputs for the next tensor stage)
#pragma unroll
    for (int im = 0; im < 2; im++) {
#pragma unroll
        for (int in_ = 0; in_ < 8; in_++) {
            int row = m0 + wm * 32 + im * 16 + r;
            int col = n0 + wn * 64 + in_ * 8 + 2 * cq;
            float4 v;
            v.x = acc[im][in_][0]; v.y = acc[im][in_][1];
            v.z = acc[im][in_][2]; v.w = acc[im][in_][3];
            if (round_out) {
                v.x = __uint_as_float(f2tf32(v.x));
                v.y = __uint_as_float(f2tf32(v.y));
                v.z = __uint_as_float(f2tf32(v.z));
                v.w = __uint_as_float(f2tf32(v.w));
            }
            *(float2*)(C + (size_t)row * N + col) = make_float2(v.x, v.y);
            *(float2*)(C + (size_t)(row + 8) * N + col) = make_float2(v.z, v.w);
        }
    }
}

// ---------------------------------------------------------------------------
// Flash attention, tf32 MMA, base-2 softmax, cp.async double-buffered K/V.
// grid = (B*H, S/128), 256 threads (8 warps), warp = 16 query rows.
// Dynamic SMEM: Ks[2][64][68] + Vs[2][64][72] = 71680 B.
// Writes z tf32-rounded in scrambled layout: z[b, h*128+s/16, (s%16)*64+d]
// ---------------------------------------------------------------------------
__global__ __launch_bounds__(256, 2) void attn_kernel(
    const float* __restrict__ qkv, float* __restrict__ z)
{
    extern __shared__ float sm_a[];
    typedef float KsT[64][68];
    typedef float VsT[64][72];
    KsT* Ks = (KsT*)sm_a;
    VsT* Vs = (VsT*)(sm_a + 2 * 64 * 68);

    const int bh = blockIdx.x;
    const int b = bh >> 4;
    const int h = bh & 15;
    const int s0 = blockIdx.y * 128;
    const int tid = threadIdx.x;
    const int lane = tid & 31;
    const int warp = tid >> 5;
    const int r = lane >> 2;
    const int cq = lane & 3;

    const float* base = qkv + (size_t)b * SS * QKVN + h * DD;

    // Q fragments scaled by (1/8)*log2(e) so softmax runs in base-2 domain.
    const float QSCALE = 0.125f * 1.44269504088896340736f;
    uint32_t qa[8][4];
    {
        const int row0 = s0 + warp * 16 + r;
        const float* q0 = base + (size_t)row0 * QKVN;
        const float* q1 = base + (size_t)(row0 + 8) * QKVN;
#pragma unroll
        for (int kf = 0; kf < 8; kf++) {
            qa[kf][0] = f2tf32(QSCALE * q0[kf * 8 + cq]);
            qa[kf][1] = f2tf32(QSCALE * q1[kf * 8 + cq]);
            qa[kf][2] = f2tf32(QSCALE * q0[kf * 8 + cq + 4]);
            qa[kf][3] = f2tf32(QSCALE * q1[kf * 8 + cq + 4]);
        }
    }

    auto load_kv = [&](int buf, int kt) {
#pragma unroll
        for (int i = 0; i < 4; i++) {
            int f = i * 256 + tid;
            int t = f >> 4;
            int c4 = (f & 15) * 4;
            const float* row = base + (size_t)(kt + t) * QKVN + c4;
            cp16(&Ks[buf][t][c4], row + 1024);
            cp16(&Vs[buf][t][c4], row + 2048);
        }
        CP_COMMIT();
    };

    float o[8][4];
#pragma unroll
    for (int nt = 0; nt < 8; nt++)
#pragma unroll
        for (int q = 0; q < 4; q++) o[nt][q] = 0.f;
    float mrow0 = -1e30f, mrow1 = -1e30f;
    float lrow0 = 0.f, lrow1 = 0.f;

    load_kv(0, 0);

    for (int it = 0; it < SS / 64; it++) {
        const int cur = it & 1;
        CP_WAIT0();
        __syncthreads();
        if (it + 1 < SS / 64) load_kv(cur ^ 1, (it + 1) * 64);

        // S = Q @ K^T (warp: 16 x 64), scores already in log2 domain
        float s[8][4];
#pragma unroll
        for (int nt = 0; nt < 8; nt++)
#pragma unroll
            for (int q = 0; q < 4; q++) s[nt][q] = 0.f;
#pragma unroll
        for (int kf = 0; kf < 8; kf++) {
#pragma unroll
            for (int nt = 0; nt < 8; nt++) {
                uint32_t bf[2];
                bf[0] = F2U(Ks[cur][nt * 8 + r][kf * 8 + cq]);
                bf[1] = F2U(Ks[cur][nt * 8 + r][kf * 8 + cq + 4]);
                mma_tf32(s[nt], qa[kf], bf);
            }
        }

        // Online softmax (base 2)
        float mt0 = -1e30f, mt1 = -1e30f;
#pragma unroll
        for (int nt = 0; nt < 8; nt++) {
            mt0 = fmaxf(mt0, fmaxf(s[nt][0], s[nt][1]));
            mt1 = fmaxf(mt1, fmaxf(s[nt][2], s[nt][3]));
        }
        mt0 = fmaxf(mt0, __shfl_xor_sync(0xffffffffu, mt0, 1));
        mt0 = fmaxf(mt0, __shfl_xor_sync(0xffffffffu, mt0, 2));
        mt1 = fmaxf(mt1, __shfl_xor_sync(0xffffffffu, mt1, 1));
        mt1 = fmaxf(mt1, __shfl_xor_sync(0xffffffffu, mt1, 2));
        float mn0 = fmaxf(mrow0, mt0);
        float mn1 = fmaxf(mrow1, mt1);
        float corr0 = ex2(mrow0 - mn0);
        float corr1 = ex2(mrow1 - mn1);
        float ls0 = 0.f, ls1 = 0.f;
#pragma unroll
        for (int nt = 0; nt < 8; nt++) {
            float p0 = ex2(s[nt][0] - mn0);
            float p1 = ex2(s[nt][1] - mn0);
            float p2 = ex2(s[nt][2] - mn1);
            float p3 = ex2(s[nt][3] - mn1);
            ls0 += p0 + p1;
            ls1 += p2 + p3;
            // reuse s[] as tf32-rounded P (bit pattern in float regs)
            s[nt][0] = __uint_as_float(f2tf32(p0));
            s[nt][1] = __uint_as_float(f2tf32(p1));
            s[nt][2] = __uint_as_float(f2tf32(p2));
            s[nt][3] = __uint_as_float(f2tf32(p3));
        }
        ls0 += __shfl_xor_sync(0xffffffffu, ls0, 1);
        ls0 += __shfl_xor_sync(0xffffffffu, ls0, 2);
        ls1 += __shfl_xor_sync(0xffffffffu, ls1, 1);
        ls1 += __shfl_xor_sync(0xffffffffu, ls1, 2);
        lrow0 = lrow0 * corr0 + ls0;
        lrow1 = lrow1 * corr1 + ls1;
        mrow0 = mn0;
        mrow1 = mn1;
#pragma unroll
        for (int nt = 0; nt < 8; nt++) {
            o[nt][0] *= corr0;
            o[nt][1] *= corr0;
            o[nt][2] *= corr1;
            o[nt][3] *= corr1;
        }

        // O += P @ V. Relayout P (C-frag) -> A-frag via intra-quad shuffles.
        const int src1 = (lane & ~3) | (cq >> 1);
        const int src2 = src1 + 2;
        const bool oddc = (cq & 1);
#pragma unroll
        for (int ks = 0; ks < 8; ks++) {
            uint32_t pa[4];
            {
                float v0 = __shfl_sync(0xffffffffu, s[ks][0], src1);
                float v1 = __shfl_sync(0xffffffffu, s[ks][1], src1);
                pa[0] = F2U(oddc ? v1 : v0);
                float w0 = __shfl_sync(0xffffffffu, s[ks][0], src2);
                float w1 = __shfl_sync(0xffffffffu, s[ks][1], src2);
                pa[2] = F2U(oddc ? w1 : w0);
                float x0 = __shfl_sync(0xffffffffu, s[ks][2], src1);
                float x1 = __shfl_sync(0xffffffffu, s[ks][3], src1);
                pa[1] = F2U(oddc ? x1 : x0);
                float y0 = __shfl_sync(0xffffffffu, s[ks][2], src2);
                float y1 = __shfl_sync(0xffffffffu, s[ks][3], src2);
                pa[3] = F2U(oddc ? y1 : y0);
            }
#pragma unroll
            for (int nt = 0; nt < 8; nt++) {
                uint32_t bf[2];
                bf[0] = F2U(Vs[cur][ks * 8 + cq][nt * 8 + r]);
                bf[1] = F2U(Vs[cur][ks * 8 + cq + 4][nt * 8 + r]);
                mma_tf32(o[nt], pa, bf);
            }
        }
    }

    // Epilogue: normalize, tf32-round, write scrambled layout
    float inv0 = 1.f / lrow0;
    float inv1 = 1.f / lrow1;
    int sg0 = s0 + warp * 16 + r;
    int sg1 = sg0 + 8;
    int zr0 = h * 128 + (sg0 >> 4);
    int zr1 = h * 128 + (sg1 >> 4);
    float* d0 = z + ((size_t)b * SS + zr0) * EE + (sg0 & 15) * 64;
    float* d1 = z + ((size_t)b * SS + zr1) * EE + (sg1 & 15) * 64;
#pragma unroll
    for (int nt = 0; nt < 8; nt++) {
        int col = nt * 8 + 2 * cq;
        float2 a0, a1;
        a0.x = __uint_as_float(f2tf32(o[nt][0] * inv0));
        a0.y = __uint_as_float(f2tf32(o[nt][1] * inv0));
        a1.x = __uint_as_float(f2tf32(o[nt][2] * inv1));
        a1.y = __uint_as_float(f2tf32(o[nt][3] * inv1));
        *(float2*)(d0 + col) = a0;
        *(float2*)(d1 + col) = a1;
    }
}

// ---------------------------------------------------------------------------
extern "C" void kernel_launch(void* const* d_in, const int* in_sizes, int n_in,
                              void* d_out, int out_size)
{
    (void)in_sizes; (void)n_in; (void)out_size;
    const float* x    = (const float*)d_in[0];
    const float* Wqkv = (const float*)d_in[1];
    const float* Wout = (const float*)d_in[2];
    float* out = (float*)d_out;

    void *p_qkv, *p_z, *p_xr, *p_wq, *p_wo;
    cudaGetSymbolAddress(&p_qkv, g_qkv);
    cudaGetSymbolAddress(&p_z, g_z);
    cudaGetSymbolAddress(&p_xr, g_xr);
    cudaGetSymbolAddress(&p_wq, g_wqkv);
    cudaGetSymbolAddress(&p_wo, g_wout);
    float* qkv = (float*)p_qkv;
    float* zb  = (float*)p_z;
    float* xr  = (float*)p_xr;
    float* wq  = (float*)p_wq;
    float* wo  = (float*)p_wo;

    const int SMEM = 71680;
    cudaFuncSetAttribute(tgemm_kernel,
                         cudaFuncAttributeMaxDynamicSharedMemorySize, SMEM);
    cudaFuncSetAttribute(attn_kernel,
                         cudaFuncAttributeMaxDynamicSharedMemorySize, SMEM);

    dim3 blk(256);
    // 0) Pre-round inputs to tf32 values
    {
        int n4x = MROWS * EE / 4;
        int n4q = EE * QKVN / 4;
        int n4o = EE * EE / 4;
        round_tf32_kernel<<<(n4x + 255) / 256, blk>>>((const float4*)x,
                                                      (float4*)xr, n4x);
        round_tf32_kernel<<<(n4q + 255) / 256, blk>>>((const float4*)Wqkv,
                                                      (float4*)wq, n4q);
        round_tf32_kernel<<<(n4o + 255) / 256, blk>>>((const float4*)Wout,
                                                      (float4*)wo, n4o);
    }
    // 1) QKV projection (round outputs to tf32 for attention)
    tgemm_kernel<<<dim3(QKVN / 128, MROWS / 128), blk, SMEM>>>(
        xr, wq, qkv, MROWS, QKVN, EE, 1);
    // 2) Attention (writes tf32-rounded scrambled z)
    attn_kernel<<<dim3(BB * HH, SS / 128), blk, SMEM>>>(qkv, zb);
    // 3) Output projection (full fp32 output)
    tgemm_kernel<<<dim3(EE / 128, MROWS / 128), blk, SMEM>>>(
        zb, wo, out, MROWS, EE, EE, 0);
}